// round 1
// baseline (speedup 1.0000x reference)
#include <cuda_runtime.h>
#include <cstddef>

// Problem constants
#define B_  2
#define S_  400
#define D_  512
#define ROWS (B_ * S_)          // 800
#define ATTN_OUT_ELEMS (S_ * B_ * D_)   // 409600
#define ALIGN_OFF ATTN_OUT_ELEMS

// Scratch (device globals: no allocation allowed)
__device__ float g_wq[ROWS * D_];
__device__ float g_uh[ROWS * D_];
__device__ float g_ctx[ROWS * D_];
__device__ float g_scores[ROWS * S_];

__device__ __forceinline__ float tanh_fast(float x) {
    float y;
    asm("tanh.approx.f32 %0, %1;" : "=f"(y) : "f"(x));
    return y;
}

// ---------------------------------------------------------------------------
// Generic register-tiled fp32 GEMM: C = A*B (+ A2*B2) (+ bias)
//  A: [M,K] row stride lda (base shifted by z*az), B: [K,N] row stride ldb
//  cmode 0: C[z*cz + r*N + c]
//  cmode 1: attn_h layout: r -> (t = r%400, b = r/400), C[t*1024 + b*512 + c]
// BM=BN=64, BK=16, 256 threads, 4x4 per thread. N%64==0, K%16==0 assumed.
// ---------------------------------------------------------------------------
#define BM 64
#define BN 64
#define BK 16

__global__ void gemm_kernel(const float* __restrict__ A, const float* __restrict__ A2,
                            int lda, int az,
                            const float* __restrict__ Bm, const float* __restrict__ B2,
                            int ldb, int bz,
                            const float* __restrict__ bias,
                            float* __restrict__ C, int cz,
                            int M, int N, int K, int cmode)
{
    __shared__ float As[BK][BM + 4];
    __shared__ float Bs[BK][BN];

    const int tid = threadIdx.x;        // 0..255
    const int tx  = tid % 16;
    const int ty  = tid / 16;
    const int row0 = blockIdx.y * BM;
    const int col0 = blockIdx.x * BN;
    const int z = blockIdx.z;

    const float* Aptr = A + (size_t)z * az;
    const float* Bptr = Bm + (size_t)z * bz;

    float acc[4][4];
    #pragma unroll
    for (int i = 0; i < 4; ++i)
        #pragma unroll
        for (int j = 0; j < 4; ++j) acc[i][j] = 0.0f;

    for (int pass = 0; pass < 2; ++pass) {
        if (pass == 1) {
            if (A2 == nullptr) break;
            Aptr = A2;
            Bptr = B2;
        }
        for (int k0 = 0; k0 < K; k0 += BK) {
            // Load A tile (64 x 16), float4 along K
            {
                const int e = tid * 4;            // 0..1023
                const int r = e / BK;             // 0..63
                const int c = e % BK;             // 0,4,8,12
                const int grow = row0 + r;
                float4 av = make_float4(0.f, 0.f, 0.f, 0.f);
                if (grow < M)
                    av = *reinterpret_cast<const float4*>(Aptr + (size_t)grow * lda + k0 + c);
                As[c + 0][r] = av.x;
                As[c + 1][r] = av.y;
                As[c + 2][r] = av.z;
                As[c + 3][r] = av.w;
            }
            // Load B tile (16 x 64), float4 along N
            {
                const int e  = tid * 4;
                const int kk = e / BN;            // 0..15
                const int c  = e % BN;
                *reinterpret_cast<float4*>(&Bs[kk][c]) =
                    *reinterpret_cast<const float4*>(Bptr + (size_t)(k0 + kk) * ldb + col0 + c);
            }
            __syncthreads();
            #pragma unroll
            for (int k = 0; k < BK; ++k) {
                float4 a4 = *reinterpret_cast<const float4*>(&As[k][ty * 4]);
                float4 b4 = *reinterpret_cast<const float4*>(&Bs[k][tx * 4]);
                float av[4] = {a4.x, a4.y, a4.z, a4.w};
                float bv[4] = {b4.x, b4.y, b4.z, b4.w};
                #pragma unroll
                for (int i = 0; i < 4; ++i)
                    #pragma unroll
                    for (int j = 0; j < 4; ++j)
                        acc[i][j] = fmaf(av[i], bv[j], acc[i][j]);
            }
            __syncthreads();
        }
    }

    #pragma unroll
    for (int i = 0; i < 4; ++i) {
        const int r = row0 + ty * 4 + i;
        if (r >= M) continue;
        #pragma unroll
        for (int j = 0; j < 4; ++j) {
            const int cc = col0 + tx * 4 + j;
            float val = acc[i][j];
            if (bias) val += bias[cc];
            size_t idx;
            if (cmode == 0) {
                idx = (size_t)z * cz + (size_t)r * N + cc;
            } else {
                const int t = r % S_;
                const int b = r / S_;
                idx = (size_t)t * (B_ * D_) + (size_t)b * D_ + cc;
            }
            C[idx] = val;
        }
    }
}

// ---------------------------------------------------------------------------
// Scores: score[b,t,s] = sum_e v[e] * tanh(wq[b,t,e] + uh[b,s,e])
// Block handles TT=8 query rows x ST=80 key rows; uh reused 8x from registers.
// grid: (S/ST=5, T/TT=50, B), 256 threads (8 warps, 10 s per warp).
// ---------------------------------------------------------------------------
#define TT 8
#define ST 80

__global__ void scores_kernel(const float* __restrict__ wq, const float* __restrict__ uh,
                              const float* __restrict__ v, float* __restrict__ scores)
{
    const int b  = blockIdx.z;
    const int t0 = blockIdx.y * TT;
    const int s0 = blockIdx.x * ST;

    __shared__ float qsm[TT][D_];
    __shared__ float vsm[D_];

    const int tid = threadIdx.x;
    for (int i = tid; i < TT * D_; i += 256) {
        const int t = i / D_;
        const int e = i % D_;
        qsm[t][e] = wq[((size_t)(b * S_ + t0 + t)) * D_ + e];
    }
    for (int i = tid; i < D_; i += 256) vsm[i] = v[i];
    __syncthreads();

    const int warp = tid / 32;
    const int lane = tid % 32;

    for (int si = warp; si < ST; si += 8) {
        const int s = s0 + si;
        const float* urow = uh + ((size_t)(b * S_ + s)) * D_;
        float acc[TT];
        #pragma unroll
        for (int t = 0; t < TT; ++t) acc[t] = 0.0f;

        #pragma unroll 4
        for (int i = 0; i < D_ / 32; ++i) {
            const int e = i * 32 + lane;
            const float u  = urow[e];
            const float ve = vsm[e];
            #pragma unroll
            for (int t = 0; t < TT; ++t)
                acc[t] = fmaf(ve, tanh_fast(qsm[t][e] + u), acc[t]);
        }
        #pragma unroll
        for (int t = 0; t < TT; ++t) {
            float a = acc[t];
            a += __shfl_xor_sync(0xffffffffu, a, 16);
            a += __shfl_xor_sync(0xffffffffu, a, 8);
            a += __shfl_xor_sync(0xffffffffu, a, 4);
            a += __shfl_xor_sync(0xffffffffu, a, 2);
            a += __shfl_xor_sync(0xffffffffu, a, 1);
            if (lane == 0)
                scores[((size_t)(b * S_ + t0 + t)) * S_ + s] = a;
        }
    }
}

// ---------------------------------------------------------------------------
// Masked softmax per (b,t) row; writes align into d_out at [t,B,S] layout.
// grid (T, B), 128 threads.
// ---------------------------------------------------------------------------
__global__ void softmax_kernel(const float* __restrict__ scores, const int* __restrict__ lens,
                               float* __restrict__ align_out)
{
    const int t = blockIdx.x;
    const int b = blockIdx.y;
    const int len = lens[b];
    const int tid = threadIdx.x;   // 128

    __shared__ float sm[S_];
    __shared__ float red[4];

    const float* srow = scores + ((size_t)(b * S_ + t)) * S_;

    float mx = -1e30f;
    for (int s = tid; s < S_; s += 128) {
        const bool ok = (s < len) && (s != t);
        const float val = ok ? srow[s] : -1e30f;
        sm[s] = val;
        mx = fmaxf(mx, val);
    }
    #pragma unroll
    for (int o = 16; o; o >>= 1) mx = fmaxf(mx, __shfl_xor_sync(0xffffffffu, mx, o));
    if ((tid & 31) == 0) red[tid >> 5] = mx;
    __syncthreads();
    const float bm = fmaxf(fmaxf(red[0], red[1]), fmaxf(red[2], red[3]));
    __syncthreads();

    float sum = 0.0f;
    for (int s = tid; s < S_; s += 128) {
        const float val = sm[s];
        const float e = (val > -1e29f) ? __expf(val - bm) : 0.0f;
        sm[s] = e;
        sum += e;
    }
    #pragma unroll
    for (int o = 16; o; o >>= 1) sum += __shfl_xor_sync(0xffffffffu, sum, o);
    if ((tid & 31) == 0) red[tid >> 5] = sum;
    __syncthreads();
    const float inv = 1.0f / (red[0] + red[1] + red[2] + red[3]);

    for (int s = tid; s < S_; s += 128)
        align_out[(size_t)t * (B_ * S_) + (size_t)b * S_ + s] = sm[s] * inv;
}

// ---------------------------------------------------------------------------
extern "C" void kernel_launch(void* const* d_in, const int* in_sizes, int n_in,
                              void* d_out, int out_size)
{
    const float* input  = (const float*)d_in[0];
    const float* memory = (const float*)d_in[1];
    const int*   lens   = (const int*)d_in[2];
    const float* Wq     = (const float*)d_in[3];
    const float* bq     = (const float*)d_in[4];
    const float* Wc     = (const float*)d_in[5];
    const float* v      = (const float*)d_in[6];
    const float* Wout   = (const float*)d_in[7];
    const float* bout   = (const float*)d_in[8];
    float* out = (float*)d_out;

    float *wq_p, *uh_p, *ctx_p, *sc_p;
    cudaGetSymbolAddress((void**)&wq_p,  g_wq);
    cudaGetSymbolAddress((void**)&uh_p,  g_uh);
    cudaGetSymbolAddress((void**)&ctx_p, g_ctx);
    cudaGetSymbolAddress((void**)&sc_p,  g_scores);

    // 1) wq = input @ Wq + bq   [800,512]
    gemm_kernel<<<dim3(D_ / BN, (ROWS + BM - 1) / BM, 1), 256>>>(
        input, nullptr, D_, 0, Wq, nullptr, D_, 0, bq, wq_p, 0, ROWS, D_, D_, 0);
    // 2) uh = memory @ Wc       [800,512]
    gemm_kernel<<<dim3(D_ / BN, (ROWS + BM - 1) / BM, 1), 256>>>(
        memory, nullptr, D_, 0, Wc, nullptr, D_, 0, nullptr, uh_p, 0, ROWS, D_, D_, 0);
    // 3) scores
    scores_kernel<<<dim3(S_ / ST, S_ / TT, B_), 256>>>(wq_p, uh_p, v, sc_p);
    // 4) masked softmax -> align (into d_out tail region)
    softmax_kernel<<<dim3(S_, B_), 128>>>(sc_p, lens, out + ALIGN_OFF);
    // 5) context: c[b] = align[b] @ memory[b]   (batched over b via z)
    gemm_kernel<<<dim3(D_ / BN, (S_ + BM - 1) / BM, B_), 256>>>(
        out + ALIGN_OFF, nullptr, B_ * S_, S_,     // A: align rows stride 800, z-shift 400
        memory, nullptr, D_, S_ * D_,              // B: memory[b], z-shift 204800
        nullptr, ctx_p, S_ * D_, S_, D_, S_, 0);
    // 6) attn_h = ctx @ Wout[0:512] + input @ Wout[512:1024] + bout -> [T,B,D] in d_out
    gemm_kernel<<<dim3(D_ / BN, (ROWS + BM - 1) / BM, 1), 256>>>(
        ctx_p, input, D_, 0, Wout, Wout + D_ * D_, D_, 0, bout, out, 0, ROWS, D_, D_, 1);
}

// round 3
// speedup vs baseline: 1.0721x; 1.0721x over previous
#include <cuda_runtime.h>
#include <cstdint>
#include <cstddef>

// Problem constants
#define B_  2
#define S_  400
#define D_  512
#define ROWS (B_ * S_)                  // 800
#define ALIGN_OFF (S_ * B_ * D_)        // 409600

// Scratch (device globals: no allocation allowed)
__device__ float g_wq[ROWS * D_];
__device__ float g_uh[ROWS * D_];
__device__ float g_ctx[ROWS * D_];
__device__ float g_scores[ROWS * S_];

// ---------------------------------------------------------------------------
__device__ __forceinline__ float tanh_fast(float x) {
    float y;
    asm("tanh.approx.f32 %0, %1;" : "=f"(y) : "f"(x));
    return y;
}

__device__ __forceinline__ uint32_t smem_u32(const void* p) {
    uint32_t a;
    asm("{ .reg .u64 t; cvta.to.shared.u64 t, %1; cvt.u32.u64 %0, t; }"
        : "=r"(a) : "l"(p));
    return a;
}

__device__ __forceinline__ uint32_t f2tf32(float x) {   // round-to-nearest tf32
    uint32_t r;
    asm("cvt.rna.tf32.f32 %0, %1;" : "=r"(r) : "f"(x));
    return r;
}

__device__ __forceinline__ void cp_async16(uint32_t dst, const void* src, uint32_t src_bytes) {
    asm volatile("cp.async.ca.shared.global [%0], [%1], 16, %2;"
                 :: "r"(dst), "l"(src), "r"(src_bytes) : "memory");
}

__device__ __forceinline__ void mma_tf32(float& d0, float& d1, float& d2, float& d3,
                                         uint32_t a0, uint32_t a1, uint32_t a2, uint32_t a3,
                                         uint32_t b0, uint32_t b1) {
    asm volatile(
        "mma.sync.aligned.m16n8k8.row.col.f32.tf32.tf32.f32 "
        "{%0,%1,%2,%3}, {%4,%5,%6,%7}, {%8,%9}, {%0,%1,%2,%3};"
        : "+f"(d0), "+f"(d1), "+f"(d2), "+f"(d3)
        : "r"(a0), "r"(a1), "r"(a2), "r"(a3), "r"(b0), "r"(b1));
}

// ---------------------------------------------------------------------------
// tf32 mma.sync GEMM: C[M,N] = A[M,K] @ B[K,N] (+bias)
//  - A optionally split along K at KA into A2 (concat GEMM); both lda.
//  - B row-major [K,N] (native layouts — no transposes needed).
//  - CTA tile 128x128, BK=16, cp.async double-buffered.
//  - 8 warps: 4 along M (32 rows each), 2 along N (64 cols each).
//  cmode 0: C[z*cz + r*ldc + c]; cmode 1: [T,B,D] scatter (r -> t=r%400,b=r/400)
// ---------------------------------------------------------------------------
#define ASTRIDE 20
#define BSTRIDE 136

__global__ void __launch_bounds__(256, 1) gemm_mma(
    const float* __restrict__ A, const float* __restrict__ A2,
    int lda, int az, int KA,
    const float* __restrict__ Bm, int ldb, int bz,
    const float* __restrict__ bias,
    float* __restrict__ C, int ldc, int cz, int cmode,
    int M, int N, int K)
{
    __shared__ float As[2][128][ASTRIDE];
    __shared__ float Bs[2][16][BSTRIDE];

    const int tid  = threadIdx.x;
    const int warp = tid >> 5, lane = tid & 31;
    const int q = lane >> 2, r = lane & 3;
    const int wm = warp & 3;          // 0..3  -> M offset 32*wm
    const int wn = warp >> 2;         // 0..1  -> N offset 64*wn
    const int row0 = blockIdx.y * 128;
    const int col0 = blockIdx.x * 128;
    const int z = blockIdx.z;

    const float* Az  = A + (size_t)z * az;
    const float* Bz  = Bm + (size_t)z * bz;

    // per-thread cp.async source coordinates (2 A chunks + 2 B chunks per stage)
    // A: chunk id ca in [0,512): arow = ca>>2, ak = (ca&3)*4
    // B: chunk id cb in [0,512): brow = cb>>5, bn = (cb&31)*4
    const uint32_t asm_base = smem_u32(&As[0][0][0]);
    const uint32_t bsm_base = smem_u32(&Bs[0][0][0]);

    float acc[2][8][4];
    #pragma unroll
    for (int i = 0; i < 2; ++i)
        #pragma unroll
        for (int j = 0; j < 8; ++j)
            #pragma unroll
            for (int k = 0; k < 4; ++k) acc[i][j][k] = 0.f;

    const int nc = K >> 4;   // K % 16 == 0 for all our calls

    // ---- stage loader ----
    auto load_stage = [&](int chunk, int buf) {
        const int k0 = chunk << 4;
        #pragma unroll
        for (int it = 0; it < 2; ++it) {
            const int ca = tid + it * 256;
            const int arow = ca >> 2;
            const int ak = (ca & 3) << 2;
            const int ar = row0 + arow;
            const int kk = k0 + ak;
            const float* src;
            if (kk < KA) src = Az + (size_t)ar * lda + kk;
            else         src = A2 + (size_t)ar * lda + (kk - KA);
            const uint32_t dst = asm_base + (uint32_t)(buf * 128 * ASTRIDE + arow * ASTRIDE + ak) * 4u;
            cp_async16(dst, src, (ar < M) ? 16u : 0u);
        }
        #pragma unroll
        for (int it = 0; it < 2; ++it) {
            const int cb = tid + it * 256;
            const int brow = cb >> 5;
            const int bn = (cb & 31) << 2;
            const float* src = Bz + (size_t)(k0 + brow) * ldb + col0 + bn;
            const uint32_t dst = bsm_base + (uint32_t)(buf * 16 * BSTRIDE + brow * BSTRIDE + bn) * 4u;
            cp_async16(dst, src, 16u);
        }
        asm volatile("cp.async.commit_group;" ::: "memory");
    };

    load_stage(0, 0);

    for (int c = 0; c < nc; ++c) {
        const int buf = c & 1;
        if (c + 1 < nc) {
            load_stage(c + 1, (c + 1) & 1);
            asm volatile("cp.async.wait_group 1;" ::: "memory");
        } else {
            asm volatile("cp.async.wait_group 0;" ::: "memory");
        }
        __syncthreads();

        #pragma unroll
        for (int ks = 0; ks < 2; ++ks) {
            const int kb = ks * 8;
            // A fragments: 2 m-tiles
            uint32_t af[2][4];
            #pragma unroll
            for (int mt = 0; mt < 2; ++mt) {
                const int mrow = wm * 32 + mt * 16 + q;
                af[mt][0] = f2tf32(As[buf][mrow    ][kb + r    ]);
                af[mt][1] = f2tf32(As[buf][mrow + 8][kb + r    ]);
                af[mt][2] = f2tf32(As[buf][mrow    ][kb + r + 4]);
                af[mt][3] = f2tf32(As[buf][mrow + 8][kb + r + 4]);
            }
            // B fragments: 8 n-tiles
            uint32_t bf[8][2];
            #pragma unroll
            for (int nt = 0; nt < 8; ++nt) {
                const int ncol = wn * 64 + nt * 8 + q;
                bf[nt][0] = f2tf32(Bs[buf][kb + r    ][ncol]);
                bf[nt][1] = f2tf32(Bs[buf][kb + r + 4][ncol]);
            }
            #pragma unroll
            for (int mt = 0; mt < 2; ++mt)
                #pragma unroll
                for (int nt = 0; nt < 8; ++nt)
                    mma_tf32(acc[mt][nt][0], acc[mt][nt][1], acc[mt][nt][2], acc[mt][nt][3],
                             af[mt][0], af[mt][1], af[mt][2], af[mt][3],
                             bf[nt][0], bf[nt][1]);
        }
        __syncthreads();
    }

    // ---- epilogue ----
    float bvals[8][2];
    #pragma unroll
    for (int nt = 0; nt < 8; ++nt) {
        const int cc = col0 + wn * 64 + nt * 8 + r * 2;
        bvals[nt][0] = bias ? __ldg(bias + cc)     : 0.f;
        bvals[nt][1] = bias ? __ldg(bias + cc + 1) : 0.f;
    }
    #pragma unroll
    for (int mt = 0; mt < 2; ++mt) {
        #pragma unroll
        for (int rh = 0; rh < 2; ++rh) {
            const int rr = row0 + wm * 32 + mt * 16 + rh * 8 + q;
            if (rr >= M) continue;
            float* rowp;
            if (cmode == 0) rowp = C + (size_t)z * cz + (size_t)rr * ldc;
            else {
                const int t = rr % S_, bb = rr / S_;
                rowp = C + (size_t)t * (B_ * D_) + (size_t)bb * D_;
            }
            #pragma unroll
            for (int nt = 0; nt < 8; ++nt) {
                const int cc = col0 + wn * 64 + nt * 8 + r * 2;
                float2 o;
                o.x = acc[mt][nt][rh * 2 + 0] + bvals[nt][0];
                o.y = acc[mt][nt][rh * 2 + 1] + bvals[nt][1];
                *(float2*)(rowp + cc) = o;
            }
        }
    }
}

// ---------------------------------------------------------------------------
// Scores: score[b,t,s] = sum_e v[e] * tanh(wq[b,t,e] + uh[b,s,e])
// 8 t per CTA; each warp processes 4 s at a time (q reused from regs).
// grid: (5, 50, 2), 256 threads. MUFU(tanh)-bound by design.
// ---------------------------------------------------------------------------
__global__ void __launch_bounds__(256) scores_kernel(
    const float* __restrict__ wq, const float* __restrict__ uh,
    const float* __restrict__ v, float* __restrict__ scores)
{
    const int b = blockIdx.z, t0 = blockIdx.y * 8;
    const int sbase = blockIdx.x * 96;
    __shared__ float qsm[8][D_];
    __shared__ float vsm[D_];
    const int tid = threadIdx.x;
    for (int i = tid; i < 8 * D_; i += 256)
        qsm[i >> 9][i & 511] = wq[((size_t)(b * S_ + t0 + (i >> 9))) * D_ + (i & 511)];
    for (int i = tid; i < D_; i += 256) vsm[i] = v[i];
    __syncthreads();
    const int warp = tid >> 5, lane = tid & 31;

    for (int sg = 0; sg < 3; ++sg) {
        const int s0 = sbase + sg * 32 + warp * 4;
        const float* up[4];
        #pragma unroll
        for (int j = 0; j < 4; ++j) {
            int sj = s0 + j; if (sj > S_ - 1) sj = S_ - 1;   // clamp (discard at store)
            up[j] = uh + ((size_t)b * S_ + sj) * D_;
        }
        float acc[8][4];
        #pragma unroll
        for (int t = 0; t < 8; ++t)
            #pragma unroll
            for (int j = 0; j < 4; ++j) acc[t][j] = 0.f;

        for (int i = 0; i < 16; ++i) {
            const int e = i * 32 + lane;
            const float ve = vsm[e];
            float qv[8];
            #pragma unroll
            for (int t = 0; t < 8; ++t) qv[t] = qsm[t][e];
            #pragma unroll
            for (int j = 0; j < 4; ++j) {
                const float u = __ldg(up[j] + e);
                #pragma unroll
                for (int t = 0; t < 8; ++t)
                    acc[t][j] = fmaf(ve, tanh_fast(qv[t] + u), acc[t][j]);
            }
        }
        #pragma unroll
        for (int t = 0; t < 8; ++t)
            #pragma unroll
            for (int j = 0; j < 4; ++j) {
                float a = acc[t][j];
                a += __shfl_xor_sync(0xffffffffu, a, 16);
                a += __shfl_xor_sync(0xffffffffu, a, 8);
                a += __shfl_xor_sync(0xffffffffu, a, 4);
                a += __shfl_xor_sync(0xffffffffu, a, 2);
                a += __shfl_xor_sync(0xffffffffu, a, 1);
                if (lane == t * 4 + j && s0 + j < S_)
                    scores[((size_t)(b * S_ + t0 + t)) * S_ + s0 + j] = a;
            }
    }
}

// ---------------------------------------------------------------------------
// Masked softmax per (b,t) row; writes align to d_out in [t,B,S] layout.
// ---------------------------------------------------------------------------
__global__ void softmax_kernel(const float* __restrict__ scores, const int* __restrict__ lens,
                               float* __restrict__ align_out)
{
    const int t = blockIdx.x;
    const int b = blockIdx.y;
    const int len = lens[b];
    const int tid = threadIdx.x;   // 128

    __shared__ float sm[S_];
    __shared__ float red[4];

    const float* srow = scores + ((size_t)(b * S_ + t)) * S_;

    float mx = -1e30f;
    for (int s = tid; s < S_; s += 128) {
        const bool ok = (s < len) && (s != t);
        const float val = ok ? srow[s] : -1e30f;
        sm[s] = val;
        mx = fmaxf(mx, val);
    }
    #pragma unroll
    for (int o = 16; o; o >>= 1) mx = fmaxf(mx, __shfl_xor_sync(0xffffffffu, mx, o));
    if ((tid & 31) == 0) red[tid >> 5] = mx;
    __syncthreads();
    const float bm = fmaxf(fmaxf(red[0], red[1]), fmaxf(red[2], red[3]));
    __syncthreads();

    float sum = 0.0f;
    for (int s = tid; s < S_; s += 128) {
        const float val = sm[s];
        const float e = (val > -1e29f) ? __expf(val - bm) : 0.0f;
        sm[s] = e;
        sum += e;
    }
    #pragma unroll
    for (int o = 16; o; o >>= 1) sum += __shfl_xor_sync(0xffffffffu, sum, o);
    if ((tid & 31) == 0) red[tid >> 5] = sum;
    __syncthreads();
    const float inv = 1.0f / (red[0] + red[1] + red[2] + red[3]);

    for (int s = tid; s < S_; s += 128)
        align_out[(size_t)t * (B_ * S_) + (size_t)b * S_ + s] = sm[s] * inv;
}

// ---------------------------------------------------------------------------
extern "C" void kernel_launch(void* const* d_in, const int* in_sizes, int n_in,
                              void* d_out, int out_size)
{
    const float* input  = (const float*)d_in[0];
    const float* memory = (const float*)d_in[1];
    const int*   lens   = (const int*)d_in[2];
    const float* Wq     = (const float*)d_in[3];
    const float* bq     = (const float*)d_in[4];
    const float* Wc     = (const float*)d_in[5];
    const float* v      = (const float*)d_in[6];
    const float* Wout   = (const float*)d_in[7];
    const float* bout   = (const float*)d_in[8];
    float* out = (float*)d_out;

    float *wq_p, *uh_p, *ctx_p, *sc_p;
    cudaGetSymbolAddress((void**)&wq_p,  g_wq);
    cudaGetSymbolAddress((void**)&uh_p,  g_uh);
    cudaGetSymbolAddress((void**)&ctx_p, g_ctx);
    cudaGetSymbolAddress((void**)&sc_p,  g_scores);

    // 1) wq = input @ Wq + bq   [800,512]
    gemm_mma<<<dim3(4, 7, 1), 256>>>(
        input, input, 512, 0, 512, Wq, 512, 0, bq, wq_p, 512, 0, 0, 800, 512, 512);
    // 2) uh = memory @ Wc       [800,512]
    gemm_mma<<<dim3(4, 7, 1), 256>>>(
        memory, memory, 512, 0, 512, Wc, 512, 0, nullptr, uh_p, 512, 0, 0, 800, 512, 512);
    // 3) scores
    scores_kernel<<<dim3(5, 50, 2), 256>>>(wq_p, uh_p, v, sc_p);
    // 4) masked softmax -> align (d_out tail)
    softmax_kernel<<<dim3(400, 2), 128>>>(sc_p, lens, out + ALIGN_OFF);
    // 5) context: c[b] = align[b] @ memory[b]  (align rows stride 800, z-shift 400)
    gemm_mma<<<dim3(4, 4, 2), 256>>>(
        out + ALIGN_OFF, out + ALIGN_OFF, 800, 400, 400,
        memory, 512, S_ * D_, nullptr, ctx_p, 512, S_ * D_, 0, 400, 512, 400);
    // 6) attn_h = [ctx | input] @ Wout + bout -> [T,B,D] in d_out
    gemm_mma<<<dim3(4, 7, 1), 256>>>(
        ctx_p, input, 512, 0, 512, Wout, 512, 0, bout, out, 512, 0, 1, 800, 512, 1024);
}

// round 4
// speedup vs baseline: 1.6105x; 1.5023x over previous
#include <cuda_runtime.h>
#include <cstdint>
#include <cstddef>

// Problem constants
#define B_  2
#define S_  400
#define D_  512
#define ROWS (B_ * S_)                  // 800
#define ALIGN_OFF (S_ * B_ * D_)        // 409600

// Scratch (device globals: no allocation allowed)
__device__ float g_wq[ROWS * D_];
__device__ float g_uh[ROWS * D_];
__device__ float g_ctx[ROWS * D_];
__device__ float g_scores[ROWS * S_];

// ---------------------------------------------------------------------------
__device__ __forceinline__ float tanh_fast(float x) {
    float y;
    asm("tanh.approx.f32 %0, %1;" : "=f"(y) : "f"(x));
    return y;
}

__device__ __forceinline__ uint32_t smem_u32(const void* p) {
    uint32_t a;
    asm("{ .reg .u64 t; cvta.to.shared.u64 t, %1; cvt.u32.u64 %0, t; }"
        : "=r"(a) : "l"(p));
    return a;
}

__device__ __forceinline__ uint32_t f2tf32(float x) {   // round-to-nearest tf32
    uint32_t r;
    asm("cvt.rna.tf32.f32 %0, %1;" : "=r"(r) : "f"(x));
    return r;
}

__device__ __forceinline__ void cp_async16(uint32_t dst, const void* src, uint32_t src_bytes) {
    asm volatile("cp.async.ca.shared.global [%0], [%1], 16, %2;"
                 :: "r"(dst), "l"(src), "r"(src_bytes) : "memory");
}

__device__ __forceinline__ void mma_tf32(float& d0, float& d1, float& d2, float& d3,
                                         uint32_t a0, uint32_t a1, uint32_t a2, uint32_t a3,
                                         uint32_t b0, uint32_t b1) {
    asm volatile(
        "mma.sync.aligned.m16n8k8.row.col.f32.tf32.tf32.f32 "
        "{%0,%1,%2,%3}, {%4,%5,%6,%7}, {%8,%9}, {%0,%1,%2,%3};"
        : "+f"(d0), "+f"(d1), "+f"(d2), "+f"(d3)
        : "r"(a0), "r"(a1), "r"(a2), "r"(a3), "r"(b0), "r"(b1));
}

struct GemmArgs {
    const float* A;     // [M, KA] row-major, lda
    const float* A2;    // [M, K-KA] row-major, lda (concat tail)
    const float* B;     // [K, N] row-major, ldb
    const float* bias;  // [N] or null
    float* C;
};

// ---------------------------------------------------------------------------
// tf32 mma.sync GEMM, 64x64 CTA tile, 128 threads (4 warps, 2x2), BK=16,
// cp.async double-buffered. blockIdx.z selects g0/g1 (fused independent GEMMs
// or per-batch operands). cmode 0: C[r*ldc+c]; cmode 1: [T,B,D] scatter.
// ---------------------------------------------------------------------------
#define ASTR 20
#define BSTR 72

__global__ void __launch_bounds__(128, 1) gemm_mma64(
    GemmArgs g0, GemmArgs g1, int lda, int KA, int ldb, int ldc, int cmode,
    int M, int N, int K)
{
    __shared__ float As[2][64][ASTR];
    __shared__ float Bs[2][16][BSTR];

    const GemmArgs g = blockIdx.z ? g1 : g0;

    const int tid  = threadIdx.x;                  // 0..127
    const int warp = tid >> 5, lane = tid & 31;
    const int q = lane >> 2, r = lane & 3;
    const int wm = warp & 1;                       // M offset 32*wm
    const int wn = warp >> 1;                      // N offset 32*wn
    const int row0 = blockIdx.y * 64;
    const int col0 = blockIdx.x * 64;

    const uint32_t asm_base = smem_u32(&As[0][0][0]);
    const uint32_t bsm_base = smem_u32(&Bs[0][0][0]);

    float acc[2][4][4];
    #pragma unroll
    for (int i = 0; i < 2; ++i)
        #pragma unroll
        for (int j = 0; j < 4; ++j)
            #pragma unroll
            for (int k = 0; k < 4; ++k) acc[i][j][k] = 0.f;

    const int nc = K >> 4;     // K % 16 == 0 for all calls

    auto load_stage = [&](int chunk, int buf) {
        const int k0 = chunk << 4;
        #pragma unroll
        for (int it = 0; it < 2; ++it) {
            const int ca = tid + it * 128;         // 0..255
            const int arow = ca >> 2;              // 0..63
            const int ak = (ca & 3) << 2;          // 0,4,8,12
            const int ar = row0 + arow;
            const int arc = (ar < M) ? ar : (M - 1);
            const int kk = k0 + ak;
            const float* src = (kk < KA) ? g.A  + (size_t)arc * lda + kk
                                         : g.A2 + (size_t)arc * lda + (kk - KA);
            const uint32_t dst = asm_base +
                (uint32_t)(buf * 64 * ASTR + arow * ASTR + ak) * 4u;
            cp_async16(dst, src, (ar < M) ? 16u : 0u);
        }
        #pragma unroll
        for (int it = 0; it < 2; ++it) {
            const int cb = tid + it * 128;         // 0..255
            const int brow = cb >> 4;              // 0..15
            const int bn = (cb & 15) << 2;         // 0..60
            const float* src = g.B + (size_t)(k0 + brow) * ldb + col0 + bn;
            const uint32_t dst = bsm_base +
                (uint32_t)(buf * 16 * BSTR + brow * BSTR + bn) * 4u;
            cp_async16(dst, src, 16u);
        }
        asm volatile("cp.async.commit_group;" ::: "memory");
    };

    load_stage(0, 0);

    for (int c = 0; c < nc; ++c) {
        const int buf = c & 1;
        if (c + 1 < nc) {
            load_stage(c + 1, (c + 1) & 1);
            asm volatile("cp.async.wait_group 1;" ::: "memory");
        } else {
            asm volatile("cp.async.wait_group 0;" ::: "memory");
        }
        __syncthreads();

        #pragma unroll
        for (int ks = 0; ks < 2; ++ks) {
            const int kb = ks * 8;
            uint32_t af[2][4];
            #pragma unroll
            for (int mt = 0; mt < 2; ++mt) {
                const int mrow = wm * 32 + mt * 16 + q;
                af[mt][0] = f2tf32(As[buf][mrow    ][kb + r    ]);
                af[mt][1] = f2tf32(As[buf][mrow + 8][kb + r    ]);
                af[mt][2] = f2tf32(As[buf][mrow    ][kb + r + 4]);
                af[mt][3] = f2tf32(As[buf][mrow + 8][kb + r + 4]);
            }
            uint32_t bf[4][2];
            #pragma unroll
            for (int nt = 0; nt < 4; ++nt) {
                const int ncol = wn * 32 + nt * 8 + q;
                bf[nt][0] = f2tf32(Bs[buf][kb + r    ][ncol]);
                bf[nt][1] = f2tf32(Bs[buf][kb + r + 4][ncol]);
            }
            #pragma unroll
            for (int mt = 0; mt < 2; ++mt)
                #pragma unroll
                for (int nt = 0; nt < 4; ++nt)
                    mma_tf32(acc[mt][nt][0], acc[mt][nt][1], acc[mt][nt][2], acc[mt][nt][3],
                             af[mt][0], af[mt][1], af[mt][2], af[mt][3],
                             bf[nt][0], bf[nt][1]);
        }
        __syncthreads();
    }

    // ---- epilogue ----
    float bvals[4][2];
    #pragma unroll
    for (int nt = 0; nt < 4; ++nt) {
        const int cc = col0 + wn * 32 + nt * 8 + r * 2;
        bvals[nt][0] = g.bias ? __ldg(g.bias + cc)     : 0.f;
        bvals[nt][1] = g.bias ? __ldg(g.bias + cc + 1) : 0.f;
    }
    #pragma unroll
    for (int mt = 0; mt < 2; ++mt) {
        #pragma unroll
        for (int rh = 0; rh < 2; ++rh) {
            const int rr = row0 + wm * 32 + mt * 16 + rh * 8 + q;
            if (rr >= M) continue;
            float* rowp;
            if (cmode == 0) rowp = g.C + (size_t)rr * ldc;
            else {
                const int t = rr % S_, bb = rr / S_;
                rowp = g.C + (size_t)t * (B_ * D_) + (size_t)bb * D_;
            }
            #pragma unroll
            for (int nt = 0; nt < 4; ++nt) {
                const int cc = col0 + wn * 32 + nt * 8 + r * 2;
                float2 o;
                o.x = acc[mt][nt][rh * 2 + 0] + bvals[nt][0];
                o.y = acc[mt][nt][rh * 2 + 1] + bvals[nt][1];
                *(float2*)(rowp + cc) = o;
            }
        }
    }
}

// ---------------------------------------------------------------------------
// Scores: score[b,t,s] = sum_e v[e] * tanh(wq[b,t,e] + uh[b,s,e])
// 8 t per CTA; each warp processes 4 s at a time (q reused from regs).
// grid: (5, 50, 2), 256 threads. MUFU(tanh)-bound by design.
// ---------------------------------------------------------------------------
__global__ void __launch_bounds__(256) scores_kernel(
    const float* __restrict__ wq, const float* __restrict__ uh,
    const float* __restrict__ v, float* __restrict__ scores)
{
    const int b = blockIdx.z, t0 = blockIdx.y * 8;
    const int sbase = blockIdx.x * 96;
    __shared__ float qsm[8][D_];
    __shared__ float vsm[D_];
    const int tid = threadIdx.x;
    for (int i = tid; i < 8 * D_; i += 256)
        qsm[i >> 9][i & 511] = wq[((size_t)(b * S_ + t0 + (i >> 9))) * D_ + (i & 511)];
    for (int i = tid; i < D_; i += 256) vsm[i] = v[i];
    __syncthreads();
    const int warp = tid >> 5, lane = tid & 31;

    for (int sg = 0; sg < 3; ++sg) {
        const int s0 = sbase + sg * 32 + warp * 4;
        const float* up[4];
        #pragma unroll
        for (int j = 0; j < 4; ++j) {
            int sj = s0 + j; if (sj > S_ - 1) sj = S_ - 1;   // clamp (discard at store)
            up[j] = uh + ((size_t)b * S_ + sj) * D_;
        }
        float acc[8][4];
        #pragma unroll
        for (int t = 0; t < 8; ++t)
            #pragma unroll
            for (int j = 0; j < 4; ++j) acc[t][j] = 0.f;

        for (int i = 0; i < 16; ++i) {
            const int e = i * 32 + lane;
            const float ve = vsm[e];
            float qv[8];
            #pragma unroll
            for (int t = 0; t < 8; ++t) qv[t] = qsm[t][e];
            #pragma unroll
            for (int j = 0; j < 4; ++j) {
                const float u = __ldg(up[j] + e);
                #pragma unroll
                for (int t = 0; t < 8; ++t)
                    acc[t][j] = fmaf(ve, tanh_fast(qv[t] + u), acc[t][j]);
            }
        }
        #pragma unroll
        for (int t = 0; t < 8; ++t)
            #pragma unroll
            for (int j = 0; j < 4; ++j) {
                float a = acc[t][j];
                a += __shfl_xor_sync(0xffffffffu, a, 16);
                a += __shfl_xor_sync(0xffffffffu, a, 8);
                a += __shfl_xor_sync(0xffffffffu, a, 4);
                a += __shfl_xor_sync(0xffffffffu, a, 2);
                a += __shfl_xor_sync(0xffffffffu, a, 1);
                if (lane == t * 4 + j && s0 + j < S_)
                    scores[((size_t)(b * S_ + t0 + t)) * S_ + s0 + j] = a;
            }
    }
}

// ---------------------------------------------------------------------------
// Masked softmax per (b,t) row; writes align to d_out in [t,B,S] layout.
// ---------------------------------------------------------------------------
__global__ void softmax_kernel(const float* __restrict__ scores, const int* __restrict__ lens,
                               float* __restrict__ align_out)
{
    const int t = blockIdx.x;
    const int b = blockIdx.y;
    const int len = lens[b];
    const int tid = threadIdx.x;   // 128

    __shared__ float sm[S_];
    __shared__ float red[4];

    const float* srow = scores + ((size_t)(b * S_ + t)) * S_;

    float mx = -1e30f;
    for (int s = tid; s < S_; s += 128) {
        const bool ok = (s < len) && (s != t);
        const float val = ok ? srow[s] : -1e30f;
        sm[s] = val;
        mx = fmaxf(mx, val);
    }
    #pragma unroll
    for (int o = 16; o; o >>= 1) mx = fmaxf(mx, __shfl_xor_sync(0xffffffffu, mx, o));
    if ((tid & 31) == 0) red[tid >> 5] = mx;
    __syncthreads();
    const float bm = fmaxf(fmaxf(red[0], red[1]), fmaxf(red[2], red[3]));
    __syncthreads();

    float sum = 0.0f;
    for (int s = tid; s < S_; s += 128) {
        const float val = sm[s];
        const float e = (val > -1e29f) ? __expf(val - bm) : 0.0f;
        sm[s] = e;
        sum += e;
    }
    #pragma unroll
    for (int o = 16; o; o >>= 1) sum += __shfl_xor_sync(0xffffffffu, sum, o);
    if ((tid & 31) == 0) red[tid >> 5] = sum;
    __syncthreads();
    const float inv = 1.0f / (red[0] + red[1] + red[2] + red[3]);

    for (int s = tid; s < S_; s += 128)
        align_out[(size_t)t * (B_ * S_) + (size_t)b * S_ + s] = sm[s] * inv;
}

// ---------------------------------------------------------------------------
extern "C" void kernel_launch(void* const* d_in, const int* in_sizes, int n_in,
                              void* d_out, int out_size)
{
    const float* input  = (const float*)d_in[0];
    const float* memory = (const float*)d_in[1];
    const int*   lens   = (const int*)d_in[2];
    const float* Wq     = (const float*)d_in[3];
    const float* bq     = (const float*)d_in[4];
    const float* Wc     = (const float*)d_in[5];
    const float* v      = (const float*)d_in[6];
    const float* Wout   = (const float*)d_in[7];
    const float* bout   = (const float*)d_in[8];
    float* out = (float*)d_out;

    float *wq_p, *uh_p, *ctx_p, *sc_p;
    cudaGetSymbolAddress((void**)&wq_p,  g_wq);
    cudaGetSymbolAddress((void**)&uh_p,  g_uh);
    cudaGetSymbolAddress((void**)&ctx_p, g_ctx);
    cudaGetSymbolAddress((void**)&sc_p,  g_scores);

    // 1) fused: z=0 -> wq = input@Wq + bq; z=1 -> uh = memory@Wc
    {
        GemmArgs gq{input,  input,  Wq, bq,      wq_p};
        GemmArgs gu{memory, memory, Wc, nullptr, uh_p};
        gemm_mma64<<<dim3(8, 13, 2), 128>>>(gq, gu, 512, 512, 512, 512, 0, 800, 512, 512);
    }
    // 2) scores
    scores_kernel<<<dim3(5, 50, 2), 256>>>(wq_p, uh_p, v, sc_p);
    // 3) masked softmax -> align (d_out tail)
    softmax_kernel<<<dim3(400, 2), 128>>>(sc_p, lens, out + ALIGN_OFF);
    // 4) context: c[b] = align[b] @ memory[b]  (align rows stride 800; z = batch)
    {
        GemmArgs c0{out + ALIGN_OFF,      out + ALIGN_OFF,      memory,           nullptr, ctx_p};
        GemmArgs c1{out + ALIGN_OFF + S_, out + ALIGN_OFF + S_, memory + S_ * D_, nullptr, ctx_p + S_ * D_};
        gemm_mma64<<<dim3(8, 7, 2), 128>>>(c0, c1, 800, 400, 512, 512, 0, 400, 512, 400);
    }
    // 5) attn_h = [ctx | input] @ Wout + bout -> [T,B,D] in d_out
    {
        GemmArgs go{ctx_p, input, Wout, bout, out};
        gemm_mma64<<<dim3(8, 13, 1), 128>>>(go, go, 512, 512, 512, 512, 1, 800, 512, 1024);
    }
}